// round 1
// baseline (speedup 1.0000x reference)
#include <cuda_runtime.h>
#include <math.h>

#define BATCH 4096
#define SEQL 512
#define DEMB 8
#define NF 32
#define DOUT 64
#define NTUP 3900            // 25 + 125 + 625 + 3125
#define LUTH_SIZE (NTUP * 32)

// LUT scratch (allowed: __device__ globals, no allocation)
__device__ __align__(128) float g_lutH[LUTH_SIZE];  // gelu(conv+b) per (tuple, filter)
__device__ __align__(128) float g_lutS[NTUP];       // attention score per tuple (sans att_b)

__device__ __forceinline__ float gelu_exact(float x) {
    return 0.5f * x * (1.0f + erff(x * 0.70710678118654752440f));
}

// ---------------------------------------------------------------------------
// Kernel A: build LUTs. One warp per tuple, lane = filter.
// ---------------------------------------------------------------------------
__global__ void build_lut_kernel(
    const float* __restrict__ emb,
    const float* __restrict__ w0, const float* __restrict__ b0, const float* __restrict__ a0,
    const float* __restrict__ w1, const float* __restrict__ b1, const float* __restrict__ a1,
    const float* __restrict__ w2, const float* __restrict__ b2, const float* __restrict__ a2,
    const float* __restrict__ w3, const float* __restrict__ b3, const float* __restrict__ a3)
{
    int gw = (blockIdx.x * blockDim.x + threadIdx.x) >> 5;
    int lane = threadIdx.x & 31;
    if (gw >= NTUP) return;

    int ks, code, baseS, baseH;
    const float *W, *Bv, *A;
    if (gw < 25)        { ks = 2; code = gw;        baseS = 0;   baseH = 0;     W = w0; Bv = b0; A = a0; }
    else if (gw < 150)  { ks = 3; code = gw - 25;   baseS = 25;  baseH = 800;   W = w1; Bv = b1; A = a1; }
    else if (gw < 775)  { ks = 4; code = gw - 150;  baseS = 150; baseH = 4800;  W = w2; Bv = b2; A = a2; }
    else                { ks = 5; code = gw - 775;  baseS = 775; baseH = 24800; W = w3; Bv = b3; A = a3; }

    float acc = Bv[lane];
    int c = code;
    for (int j = 0; j < ks; j++) {
        int t = c % 5; c /= 5;
        if (t != 4) {  // PAD row is zero
            #pragma unroll
            for (int cc = 0; cc < DEMB; cc++)
                acc += emb[t * DEMB + cc] * W[lane * DEMB * ks + cc * ks + j];
        }
    }
    float h = gelu_exact(acc);
    g_lutH[baseH + code * 32 + lane] = h;

    float sv = h * A[lane];
    #pragma unroll
    for (int o = 16; o; o >>= 1) sv += __shfl_xor_sync(0xffffffffu, sv, o);
    if (lane == 0) g_lutS[baseS + code] = sv;
}

// ---------------------------------------------------------------------------
// Kernel B: persistent main kernel. One row per loop iteration.
// ---------------------------------------------------------------------------
__global__ __launch_bounds__(256) void seqcnn_main(
    const int*   __restrict__ x_idx,
    const float* __restrict__ proj_w,
    const float* __restrict__ proj_b,
    const float* __restrict__ gamma,
    const float* __restrict__ beta,
    float*       __restrict__ out)
{
    __shared__ float pw[DOUT * 129];          // proj_w, stride 129 -> conflict-free
    __shared__ int   xrow[SEQL];
    __shared__ float sw[SEQL];                // scores then softmax numerators
    __shared__ unsigned short codes[SEQL];
    __shared__ float partial[8 * 32];
    __shared__ float feats[128];
    __shared__ float red[258];

    const int tid = threadIdx.x, lane = tid & 31, warp = tid >> 5;

    // Cache proj_w once per (persistent) block, padded stride.
    for (int i = tid; i < DOUT * 128; i += 256)
        pw[(i >> 7) * 129 + (i & 127)] = proj_w[i];

    for (int row = blockIdx.x; row < BATCH; row += gridDim.x) {
        __syncthreads();
        for (int l = tid; l < SEQL; l += 256) xrow[l] = x_idx[row * SEQL + l];
        __syncthreads();

        #pragma unroll
        for (int br = 0; br < 4; br++) {
            const int ks    = br + 2;
            const int Lp    = SEQL - ks + 1;
            const int baseS = (br == 0) ? 0 : (br == 1) ? 25  : (br == 2) ? 150  : 775;
            const int baseH = (br == 0) ? 0 : (br == 1) ? 800 : (br == 2) ? 4800 : 24800;

            // pass 0: tuple codes + scores + local max
            float lmax = -1e30f;
            for (int l = tid; l < Lp; l += 256) {
                int c = xrow[l];
                int m = 5;
                #pragma unroll
                for (int j = 1; j < 5; j++) {
                    if (j < ks) { c += xrow[l + j] * m; m *= 5; }
                }
                codes[l] = (unsigned short)c;
                float s = __ldg(&g_lutS[baseS + c]);
                sw[l] = s;
                lmax = fmaxf(lmax, s);
            }
            // block max reduce
            red[tid] = lmax; __syncthreads();
            if (tid < 128) red[tid] = fmaxf(red[tid], red[tid + 128]);
            __syncthreads();
            if (tid < 64)  red[tid] = fmaxf(red[tid], red[tid + 64]);
            __syncthreads();
            if (tid < 32) {
                float v = fmaxf(red[tid], red[tid + 32]);
                #pragma unroll
                for (int o = 16; o; o >>= 1) v = fmaxf(v, __shfl_xor_sync(0xffffffffu, v, o));
                if (tid == 0) red[256] = v;
            }
            __syncthreads();
            const float mx = red[256];

            // pass 1: exp + sum
            float lsum = 0.f;
            for (int l = tid; l < Lp; l += 256) {
                float e = __expf(sw[l] - mx);
                sw[l] = e;
                lsum += e;
            }
            red[tid] = lsum; __syncthreads();
            if (tid < 128) red[tid] += red[tid + 128];
            __syncthreads();
            if (tid < 64)  red[tid] += red[tid + 64];
            __syncthreads();
            if (tid < 32) {
                float v = red[tid] + red[tid + 32];
                #pragma unroll
                for (int o = 16; o; o >>= 1) v += __shfl_xor_sync(0xffffffffu, v, o);
                if (tid == 0) red[256] = v;
            }
            __syncthreads();
            const float invZ = 1.0f / red[256];

            // pass 2: weighted pooling. Warp over positions, lane = filter.
            const float* lut = g_lutH + baseH;
            float acc = 0.f;
            #pragma unroll 4
            for (int l = warp; l < Lp; l += 8)
                acc += __ldg(&lut[(int)codes[l] * 32 + lane]) * sw[l];
            partial[warp * 32 + lane] = acc;
            __syncthreads();
            if (tid < 32) {
                float a = 0.f;
                #pragma unroll
                for (int w = 0; w < 8; w++) a += partial[w * 32 + tid];
                feats[br * 32 + tid] = a * invZ;
            }
            __syncthreads();
        }

        // proj (128->64) + gelu + layernorm
        float z = 0.f;
        if (tid < 64) {
            float a = proj_b[tid];
            const float* pwr = &pw[tid * 129];
            #pragma unroll
            for (int k = 0; k < 128; k++) a += feats[k] * pwr[k];
            z = gelu_exact(a);
            red[tid] = z;
            red[64 + tid] = z * z;
        }
        __syncthreads();
        if (tid < 32) {
            float s = red[tid] + red[tid + 32];
            float q = red[64 + tid] + red[96 + tid];
            #pragma unroll
            for (int o = 16; o; o >>= 1) {
                s += __shfl_xor_sync(0xffffffffu, s, o);
                q += __shfl_xor_sync(0xffffffffu, q, o);
            }
            if (tid == 0) {
                float mu  = s * (1.0f / 64.0f);
                float var = q * (1.0f / 64.0f) - mu * mu;
                red[128] = mu;
                red[129] = rsqrtf(var + 1e-5f);
            }
        }
        __syncthreads();
        if (tid < 64)
            out[row * DOUT + tid] = (z - red[128]) * red[129] * gamma[tid] + beta[tid];
    }
}

// ---------------------------------------------------------------------------
extern "C" void kernel_launch(void* const* d_in, const int* in_sizes, int n_in,
                              void* d_out, int out_size)
{
    (void)in_sizes; (void)n_in; (void)out_size;
    const int*   x_idx  = (const int*)  d_in[0];
    const float* emb    = (const float*)d_in[1];
    const float* cw[4], *cb[4], *aw[4];
    for (int i = 0; i < 4; i++) {
        cw[i] = (const float*)d_in[2 + 4 * i];
        cb[i] = (const float*)d_in[3 + 4 * i];
        aw[i] = (const float*)d_in[4 + 4 * i];
        // att_b at d_in[5 + 4*i] is a constant shift -> cancels in softmax
    }
    const float* proj_w = (const float*)d_in[18];
    const float* proj_b = (const float*)d_in[19];
    const float* gamma  = (const float*)d_in[20];
    const float* beta   = (const float*)d_in[21];

    build_lut_kernel<<<488, 256>>>(emb,
        cw[0], cb[0], aw[0],
        cw[1], cb[1], aw[1],
        cw[2], cb[2], aw[2],
        cw[3], cb[3], aw[3]);

    seqcnn_main<<<740, 256>>>(x_idx, proj_w, proj_b, gamma, beta, (float*)d_out);
}

// round 2
// speedup vs baseline: 1.3257x; 1.3257x over previous
#include <cuda_runtime.h>
#include <math.h>

#define BATCH 4096
#define SEQL 512
#define DEMB 8
#define NTUP 3900            // 25 + 125 + 625 + 3125

__device__ __align__(128) float  g_lutH[NTUP * 32];   // gelu(conv+b) per (tuple, filter)
__device__ __align__(128) float  g_lutS[NTUP];        // per-branch attention scores
__device__ __align__(128) float4 g_lutS4[3125];       // combined scores keyed by 5-gram code

__device__ __forceinline__ float gelu_exact(float x) {
    return 0.5f * x * (1.0f + erff(x * 0.70710678118654752440f));
}

// ---------------------------------------------------------------------------
// Kernel A: build per-branch LUTs. One warp per tuple, lane = filter.
// ---------------------------------------------------------------------------
__global__ void build_lut_kernel(
    const float* __restrict__ emb,
    const float* __restrict__ w0, const float* __restrict__ b0, const float* __restrict__ a0,
    const float* __restrict__ w1, const float* __restrict__ b1, const float* __restrict__ a1,
    const float* __restrict__ w2, const float* __restrict__ b2, const float* __restrict__ a2,
    const float* __restrict__ w3, const float* __restrict__ b3, const float* __restrict__ a3)
{
    int gw = (blockIdx.x * blockDim.x + threadIdx.x) >> 5;
    int lane = threadIdx.x & 31;
    if (gw >= NTUP) return;

    int ks, code, baseS, baseH;
    const float *W, *Bv, *A;
    if (gw < 25)        { ks = 2; code = gw;        baseS = 0;   baseH = 0;     W = w0; Bv = b0; A = a0; }
    else if (gw < 150)  { ks = 3; code = gw - 25;   baseS = 25;  baseH = 800;   W = w1; Bv = b1; A = a1; }
    else if (gw < 775)  { ks = 4; code = gw - 150;  baseS = 150; baseH = 4800;  W = w2; Bv = b2; A = a2; }
    else                { ks = 5; code = gw - 775;  baseS = 775; baseH = 24800; W = w3; Bv = b3; A = a3; }

    float acc = Bv[lane];
    int c = code;
    for (int j = 0; j < ks; j++) {
        int t = c % 5; c /= 5;
        if (t != 4) {  // PAD row is zero
            #pragma unroll
            for (int cc = 0; cc < DEMB; cc++)
                acc += emb[t * DEMB + cc] * W[lane * DEMB * ks + cc * ks + j];
        }
    }
    float h = gelu_exact(acc);
    g_lutH[baseH + code * 32 + lane] = h;

    float sv = h * A[lane];
    #pragma unroll
    for (int o = 16; o; o >>= 1) sv += __shfl_xor_sync(0xffffffffu, sv, o);
    if (lane == 0) g_lutS[baseS + code] = sv;
}

// ---------------------------------------------------------------------------
// Kernel B: combine per-branch scores into one float4 LUT keyed by 5-gram code.
// ---------------------------------------------------------------------------
__global__ void combine_s4_kernel()
{
    int c = blockIdx.x * blockDim.x + threadIdx.x;
    if (c >= 3125) return;
    float4 s;
    s.x = g_lutS[        c % 25 ];
    s.y = g_lutS[ 25  +  c % 125];
    s.z = g_lutS[ 150 +  c % 625];
    s.w = g_lutS[ 775 +  c      ];
    g_lutS4[c] = s;
}

// ---------------------------------------------------------------------------
// Kernel C: persistent main kernel.
// ---------------------------------------------------------------------------
__global__ __launch_bounds__(256, 5) void seqcnn_main(
    const int*   __restrict__ x_idx,
    const float* __restrict__ proj_w,   // [64][128]
    const float* __restrict__ proj_b,
    const float* __restrict__ gamma,
    const float* __restrict__ beta,
    float*       __restrict__ out)
{
    __shared__ unsigned char xrow[SEQL + 8];
    __shared__ uint2  codes[SEQL];        // (c2 | c3<<16, c4 | c5<<16)
    __shared__ float4 swv[SEQL];          // softmax numerators, 4 branches
    __shared__ float4 red4[256];
    __shared__ float4 partial[4][64];     // [branch][warp*8 + fl]
    __shared__ float4 feats4[32];         // 128 pooled features
    __shared__ float  invZ[4];
    __shared__ float  lnstats[2];

    const int tid = threadIdx.x, lane = tid & 31, warp = tid >> 5;
    const int grp = lane >> 3, fl = lane & 7;
    const float4* lutH4 = (const float4*)g_lutH;

    for (int row = blockIdx.x; row < BATCH; row += gridDim.x) {
        __syncthreads();
        for (int l = tid; l < SEQL; l += 256)
            xrow[l] = (unsigned char)x_idx[row * SEQL + l];
        if (tid < 8) xrow[SEQL + tid] = 0;
        __syncthreads();

        // ---- fused pass: codes + combined scores + exp + partial sum ----
        float4 sum4 = {0.f, 0.f, 0.f, 0.f};
        for (int l = tid; l < 511; l += 256) {
            int x0 = xrow[l], x1 = xrow[l+1], x2 = xrow[l+2], x3 = xrow[l+3], x4 = xrow[l+4];
            int c2 = x0 + 5 * x1;
            int c3 = c2 + 25 * x2;
            int c4 = c3 + 125 * x3;
            int c5 = c4 + 625 * x4;
            codes[l] = make_uint2((unsigned)(c2 | (c3 << 16)), (unsigned)(c4 | (c5 << 16)));
            float4 s = __ldg(&g_lutS4[c5]);
            if (l >= 508) s.w = -1e30f;   // ks=5 valid l < 508
            if (l >= 509) s.z = -1e30f;   // ks=4 valid l < 509
            if (l >= 510) s.y = -1e30f;   // ks=3 valid l < 510
            float4 e;
            e.x = __expf(s.x); e.y = __expf(s.y); e.z = __expf(s.z); e.w = __expf(s.w);
            swv[l] = e;
            sum4.x += e.x; sum4.y += e.y; sum4.z += e.z; sum4.w += e.w;
        }
        red4[tid] = sum4;
        __syncthreads();
        if (tid < 128) {
            float4 o = red4[tid + 128];
            sum4.x += o.x; sum4.y += o.y; sum4.z += o.z; sum4.w += o.w;
            red4[tid] = sum4;
        }
        __syncthreads();
        if (tid < 64) {
            float4 a = red4[tid], o = red4[tid + 64];
            a.x += o.x; a.y += o.y; a.z += o.z; a.w += o.w;
            red4[tid] = a;
        }
        __syncthreads();
        if (tid < 32) {
            float4 v = red4[tid], o = red4[tid + 32];
            v.x += o.x; v.y += o.y; v.z += o.z; v.w += o.w;
            #pragma unroll
            for (int o2 = 16; o2; o2 >>= 1) {
                v.x += __shfl_xor_sync(0xffffffffu, v.x, o2);
                v.y += __shfl_xor_sync(0xffffffffu, v.y, o2);
                v.z += __shfl_xor_sync(0xffffffffu, v.z, o2);
                v.w += __shfl_xor_sync(0xffffffffu, v.w, o2);
            }
            if (tid == 0) {
                invZ[0] = 1.0f / v.x; invZ[1] = 1.0f / v.y;
                invZ[2] = 1.0f / v.z; invZ[3] = 1.0f / v.w;
            }
        }
        __syncthreads();

        // ---- pooling: warp covers 4 positions x 4 branches per iteration ----
        float4 a0 = {0,0,0,0}, a1 = a0, a2 = a0, a3 = a0;
        for (int base = warp * 4 + grp; base < 511; base += 32) {
            uint2  cd = codes[base];
            float4 w  = swv[base];
            int c2 = cd.x & 0xffff, c3 = cd.x >> 16;
            int c4 = cd.y & 0xffff, c5 = cd.y >> 16;
            float4 h0 = __ldg(&lutH4[        (c2 << 3) + fl]);
            float4 h1 = __ldg(&lutH4[ 200  + (c3 << 3) + fl]);
            float4 h2 = __ldg(&lutH4[ 1200 + (c4 << 3) + fl]);
            float4 h3 = __ldg(&lutH4[ 6200 + (c5 << 3) + fl]);
            a0.x += w.x * h0.x; a0.y += w.x * h0.y; a0.z += w.x * h0.z; a0.w += w.x * h0.w;
            a1.x += w.y * h1.x; a1.y += w.y * h1.y; a1.z += w.y * h1.z; a1.w += w.y * h1.w;
            a2.x += w.z * h2.x; a2.y += w.z * h2.y; a2.z += w.z * h2.z; a2.w += w.z * h2.w;
            a3.x += w.w * h3.x; a3.y += w.w * h3.y; a3.z += w.w * h3.z; a3.w += w.w * h3.w;
        }
        // reduce across the 4 groups in each warp
        #pragma unroll
        for (int o2 = 8; o2 <= 16; o2 <<= 1) {
            a0.x += __shfl_xor_sync(0xffffffffu, a0.x, o2); a0.y += __shfl_xor_sync(0xffffffffu, a0.y, o2);
            a0.z += __shfl_xor_sync(0xffffffffu, a0.z, o2); a0.w += __shfl_xor_sync(0xffffffffu, a0.w, o2);
            a1.x += __shfl_xor_sync(0xffffffffu, a1.x, o2); a1.y += __shfl_xor_sync(0xffffffffu, a1.y, o2);
            a1.z += __shfl_xor_sync(0xffffffffu, a1.z, o2); a1.w += __shfl_xor_sync(0xffffffffu, a1.w, o2);
            a2.x += __shfl_xor_sync(0xffffffffu, a2.x, o2); a2.y += __shfl_xor_sync(0xffffffffu, a2.y, o2);
            a2.z += __shfl_xor_sync(0xffffffffu, a2.z, o2); a2.w += __shfl_xor_sync(0xffffffffu, a2.w, o2);
            a3.x += __shfl_xor_sync(0xffffffffu, a3.x, o2); a3.y += __shfl_xor_sync(0xffffffffu, a3.y, o2);
            a3.z += __shfl_xor_sync(0xffffffffu, a3.z, o2); a3.w += __shfl_xor_sync(0xffffffffu, a3.w, o2);
        }
        if (grp == 0) {
            partial[0][warp * 8 + fl] = a0;
            partial[1][warp * 8 + fl] = a1;
            partial[2][warp * 8 + fl] = a2;
            partial[3][warp * 8 + fl] = a3;
        }
        __syncthreads();
        if (tid < 32) {
            int br = tid >> 3, f = tid & 7;
            float4 s = {0,0,0,0};
            #pragma unroll
            for (int w8 = 0; w8 < 8; w8++) {
                float4 p = partial[br][w8 * 8 + f];
                s.x += p.x; s.y += p.y; s.z += p.z; s.w += p.w;
            }
            float iz = invZ[br];
            s.x *= iz; s.y *= iz; s.z *= iz; s.w *= iz;
            feats4[br * 8 + f] = s;
        }
        __syncthreads();

        // ---- proj (128->64) + gelu + layernorm ----
        float z = 0.f;
        if (tid < 64) {
            float acc = __ldg(&proj_b[tid]);
            const float4* pw4 = (const float4*)proj_w + tid * 32;
            #pragma unroll
            for (int k = 0; k < 32; k++) {
                float4 f = feats4[k];
                float4 p = __ldg(&pw4[k]);
                acc += f.x * p.x + f.y * p.y + f.z * p.z + f.w * p.w;
            }
            z = gelu_exact(acc);
            red4[tid].x = z;
            red4[tid].y = z * z;
        }
        __syncthreads();
        if (tid < 32) {
            float s = red4[tid].x + red4[tid + 32].x;
            float q = red4[tid].y + red4[tid + 32].y;
            #pragma unroll
            for (int o2 = 16; o2; o2 >>= 1) {
                s += __shfl_xor_sync(0xffffffffu, s, o2);
                q += __shfl_xor_sync(0xffffffffu, q, o2);
            }
            if (tid == 0) {
                float mu  = s * (1.0f / 64.0f);
                float var = q * (1.0f / 64.0f) - mu * mu;
                lnstats[0] = mu;
                lnstats[1] = rsqrtf(var + 1e-5f);
            }
        }
        __syncthreads();
        if (tid < 64)
            out[row * 64 + tid] = (z - lnstats[0]) * lnstats[1] * __ldg(&gamma[tid]) + __ldg(&beta[tid]);
    }
}

// ---------------------------------------------------------------------------
extern "C" void kernel_launch(void* const* d_in, const int* in_sizes, int n_in,
                              void* d_out, int out_size)
{
    (void)in_sizes; (void)n_in; (void)out_size;
    const int*   x_idx  = (const int*)  d_in[0];
    const float* emb    = (const float*)d_in[1];
    const float* cw[4], *cb[4], *aw[4];
    for (int i = 0; i < 4; i++) {
        cw[i] = (const float*)d_in[2 + 4 * i];
        cb[i] = (const float*)d_in[3 + 4 * i];
        aw[i] = (const float*)d_in[4 + 4 * i];
        // att_b is a constant shift inside softmax -> cancels
    }
    const float* proj_w = (const float*)d_in[18];
    const float* proj_b = (const float*)d_in[19];
    const float* gamma  = (const float*)d_in[20];
    const float* beta   = (const float*)d_in[21];

    build_lut_kernel<<<488, 256>>>(emb,
        cw[0], cb[0], aw[0],
        cw[1], cb[1], aw[1],
        cw[2], cb[2], aw[2],
        cw[3], cb[3], aw[3]);

    combine_s4_kernel<<<13, 256>>>();

    seqcnn_main<<<740, 256>>>(x_idx, proj_w, proj_b, gamma, beta, (float*)d_out);
}

// round 3
// speedup vs baseline: 1.4164x; 1.0685x over previous
#include <cuda_runtime.h>
#include <math.h>

#define BATCH 4096
#define SEQL 512
#define NTUP 3900            // 25 + 125 + 625 + 3125
#define WH 152               // hist stride (25 + 125, padded)
#define GRID_MAIN 740

__device__ __align__(128) float  g_lutH[NTUP * 32];   // gelu(conv+b) per (tuple, filter)
__device__ __align__(128) float  g_lutS[NTUP];        // per-branch attention scores
__device__ __align__(128) float4 g_lutS4[3125];       // combined scores keyed by 5-gram code
__device__ unsigned g_row_ctr;

__device__ __forceinline__ float gelu_exact(float x) {
    return 0.5f * x * (1.0f + erff(x * 0.70710678118654752440f));
}

// ---------------------------------------------------------------------------
// Kernel A: build per-branch LUTs. One warp per tuple, lane = filter.
// Fully unrolled per kernel-size via template (emb[PAD] row is zero, so no branch).
// ---------------------------------------------------------------------------
template <int KS>
__device__ __forceinline__ void build_one(
    int code, int lane, int baseS, int baseH,
    const float* __restrict__ emb, const float* __restrict__ W,
    const float* __restrict__ Bv, const float* __restrict__ A)
{
    float acc = Bv[lane];
    int c = code;
    #pragma unroll
    for (int j = 0; j < KS; j++) {
        int t = c % 5; c /= 5;
        const float* er = emb + t * 8;
        const float* wr = W + lane * 8 * KS + j;
        #pragma unroll
        for (int cc = 0; cc < 8; cc++)
            acc += er[cc] * wr[cc * KS];
    }
    float h = gelu_exact(acc);
    g_lutH[baseH + code * 32 + lane] = h;

    float sv = h * A[lane];
    #pragma unroll
    for (int o = 16; o; o >>= 1) sv += __shfl_xor_sync(0xffffffffu, sv, o);
    if (lane == 0) g_lutS[baseS + code] = sv;
}

__global__ void build_lut_kernel(
    const float* __restrict__ emb,
    const float* __restrict__ w0, const float* __restrict__ b0, const float* __restrict__ a0,
    const float* __restrict__ w1, const float* __restrict__ b1, const float* __restrict__ a1,
    const float* __restrict__ w2, const float* __restrict__ b2, const float* __restrict__ a2,
    const float* __restrict__ w3, const float* __restrict__ b3, const float* __restrict__ a3)
{
    int gw = (blockIdx.x * blockDim.x + threadIdx.x) >> 5;
    int lane = threadIdx.x & 31;
    if (gw >= NTUP) return;

    if (gw < 25)        build_one<2>(gw,        lane, 0,   0,     emb, w0, b0, a0);
    else if (gw < 150)  build_one<3>(gw - 25,   lane, 25,  800,   emb, w1, b1, a1);
    else if (gw < 775)  build_one<4>(gw - 150,  lane, 150, 4800,  emb, w2, b2, a2);
    else                build_one<5>(gw - 775,  lane, 775, 24800, emb, w3, b3, a3);
}

// ---------------------------------------------------------------------------
// Kernel B: combine per-branch scores keyed by 5-gram code; reset row counter.
// ---------------------------------------------------------------------------
__global__ void combine_s4_kernel()
{
    int c = blockIdx.x * blockDim.x + threadIdx.x;
    if (c == 0) g_row_ctr = 0;
    if (c >= 3125) return;
    float4 s;
    s.x = g_lutS[        c % 25 ];
    s.y = g_lutS[ 25  +  c % 125];
    s.z = g_lutS[ 150 +  c % 625];
    s.w = g_lutS[ 775 +  c      ];
    g_lutS4[c] = s;
}

// ---------------------------------------------------------------------------
// Kernel C: persistent main kernel, dynamic row stealing.
// ---------------------------------------------------------------------------
__global__ __launch_bounds__(256, 5) void seqcnn_main(
    const int*   __restrict__ x_idx,
    const float* __restrict__ proj_w,   // [64][128]
    const float* __restrict__ proj_b,
    const float* __restrict__ gamma,
    const float* __restrict__ beta,
    float*       __restrict__ out)
{
    __shared__ unsigned char xrow[SEQL + 8];
    __shared__ unsigned      code45[SEQL];   // c4 | c5<<16
    __shared__ float2        swv2[SEQL];     // exp weights (ks4, ks5)
    __shared__ float         hist[8 * WH];   // per-warp ks2/ks3 weight histograms
    __shared__ float4        zred[8];        // per-warp Z partials (4 branches)
    __shared__ float4        partial[4][64]; // [branch][warp*8 + fl]
    __shared__ float4        feats4[32];     // 128 pooled features
    __shared__ float         lnred[128];
    __shared__ float         lnstats[2];

    const int tid = threadIdx.x, lane = tid & 31, warp = tid >> 5;
    const int grp = lane >> 3, fl = lane & 7;
    const float4* lutH4 = (const float4*)g_lutH;

    for (;;) {
        unsigned row;
        if (tid == 0) row = atomicAdd(&g_row_ctr, 1u);
        row = __shfl_sync(0xffffffffu, row, 0);
        __shared__ unsigned row_sh;
        if (tid == 0) row_sh = row;
        __syncthreads();
        row = row_sh;
        if (row >= BATCH) break;

        // ---- phase 0: stage row + zero hist ----
        for (int l = tid; l < SEQL; l += 256)
            xrow[l] = (unsigned char)x_idx[row * SEQL + l];
        if (tid < 8) xrow[SEQL + tid] = 0;
        for (int i = tid; i < 8 * WH; i += 256) hist[i] = 0.f;
        __syncthreads();

        // ---- phase 1: codes + scores + exp; hist for ks2/3; stash ks4/5 ----
        float4 sum4 = {0.f, 0.f, 0.f, 0.f};
        float* histW = hist + warp * WH;
        for (int l = tid; l < 511; l += 256) {
            int x0 = xrow[l], x1 = xrow[l+1], x2 = xrow[l+2], x3 = xrow[l+3], x4 = xrow[l+4];
            int c2 = x0 + 5 * x1;
            int c3 = c2 + 25 * x2;
            int c4 = c3 + 125 * x3;
            int c5 = c4 + 625 * x4;
            float4 s = __ldg(&g_lutS4[c5]);
            if (l >= 508) s.w = -1e30f;
            if (l >= 509) s.z = -1e30f;
            if (l >= 510) s.y = -1e30f;
            float ex = __expf(s.x), ey = __expf(s.y), ez = __expf(s.z), ew = __expf(s.w);
            atomicAdd(&histW[c2], ex);
            atomicAdd(&histW[25 + c3], ey);
            swv2[l] = make_float2(ez, ew);
            code45[l] = (unsigned)(c4 | (c5 << 16));
            sum4.x += ex; sum4.y += ey; sum4.z += ez; sum4.w += ew;
        }
        // warp-level Z reduce
        #pragma unroll
        for (int o = 16; o; o >>= 1) {
            sum4.x += __shfl_xor_sync(0xffffffffu, sum4.x, o);
            sum4.y += __shfl_xor_sync(0xffffffffu, sum4.y, o);
            sum4.z += __shfl_xor_sync(0xffffffffu, sum4.z, o);
            sum4.w += __shfl_xor_sync(0xffffffffu, sum4.w, o);
        }
        if (lane == 0) zred[warp] = sum4;
        __syncthreads();

        // ---- phase 2a: sparse pooling for ks4/ks5 ----
        float4 a2 = {0,0,0,0}, a3 = a2;
        for (int base = warp * 4 + grp; base < 509; base += 32) {
            unsigned cd = code45[base];
            float2 w = swv2[base];
            int c4 = cd & 0xffff, c5 = cd >> 16;
            float4 h2 = __ldg(&lutH4[1200 + (c4 << 3) + fl]);
            float4 h3 = __ldg(&lutH4[6200 + (c5 << 3) + fl]);
            a2.x += w.x * h2.x; a2.y += w.x * h2.y; a2.z += w.x * h2.z; a2.w += w.x * h2.w;
            a3.x += w.y * h3.x; a3.y += w.y * h3.y; a3.z += w.y * h3.z; a3.w += w.y * h3.w;
        }

        // ---- phase 2b: dense pooling for ks2/ks3 over 150 codes ----
        float4 a0 = {0,0,0,0}, a1 = a0;
        for (int code = warp * 4 + grp; code < 150; code += 32) {
            float wsum = 0.f;
            #pragma unroll
            for (int w8 = 0; w8 < 8; w8++) wsum += hist[w8 * WH + code];
            if (code < 25) {
                float4 h = __ldg(&lutH4[(code << 3) + fl]);
                a0.x += wsum * h.x; a0.y += wsum * h.y; a0.z += wsum * h.z; a0.w += wsum * h.w;
            } else {
                float4 h = __ldg(&lutH4[200 + ((code - 25) << 3) + fl]);
                a1.x += wsum * h.x; a1.y += wsum * h.y; a1.z += wsum * h.z; a1.w += wsum * h.w;
            }
        }

        // reduce across the 4 groups within each warp
        #pragma unroll
        for (int o = 8; o <= 16; o <<= 1) {
            a0.x += __shfl_xor_sync(0xffffffffu, a0.x, o); a0.y += __shfl_xor_sync(0xffffffffu, a0.y, o);
            a0.z += __shfl_xor_sync(0xffffffffu, a0.z, o); a0.w += __shfl_xor_sync(0xffffffffu, a0.w, o);
            a1.x += __shfl_xor_sync(0xffffffffu, a1.x, o); a1.y += __shfl_xor_sync(0xffffffffu, a1.y, o);
            a1.z += __shfl_xor_sync(0xffffffffu, a1.z, o); a1.w += __shfl_xor_sync(0xffffffffu, a1.w, o);
            a2.x += __shfl_xor_sync(0xffffffffu, a2.x, o); a2.y += __shfl_xor_sync(0xffffffffu, a2.y, o);
            a2.z += __shfl_xor_sync(0xffffffffu, a2.z, o); a2.w += __shfl_xor_sync(0xffffffffu, a2.w, o);
            a3.x += __shfl_xor_sync(0xffffffffu, a3.x, o); a3.y += __shfl_xor_sync(0xffffffffu, a3.y, o);
            a3.z += __shfl_xor_sync(0xffffffffu, a3.z, o); a3.w += __shfl_xor_sync(0xffffffffu, a3.w, o);
        }
        if (grp == 0) {
            partial[0][warp * 8 + fl] = a0;
            partial[1][warp * 8 + fl] = a1;
            partial[2][warp * 8 + fl] = a2;
            partial[3][warp * 8 + fl] = a3;
        }
        __syncthreads();

        // ---- combine warps + normalize by Z ----
        if (tid < 32) {
            int br = tid >> 3, f = tid & 7;
            float4 s = {0,0,0,0};
            #pragma unroll
            for (int w8 = 0; w8 < 8; w8++) {
                float4 p = partial[br][w8 * 8 + f];
                s.x += p.x; s.y += p.y; s.z += p.z; s.w += p.w;
            }
            float4 zt = zred[0];
            #pragma unroll
            for (int w8 = 1; w8 < 8; w8++) {
                float4 zz = zred[w8];
                zt.x += zz.x; zt.y += zz.y; zt.z += zz.z; zt.w += zz.w;
            }
            float Z = (br == 0) ? zt.x : (br == 1) ? zt.y : (br == 2) ? zt.z : zt.w;
            float iz = 1.0f / Z;
            s.x *= iz; s.y *= iz; s.z *= iz; s.w *= iz;
            feats4[br * 8 + f] = s;
        }
        __syncthreads();

        // ---- proj (128->64) + gelu + layernorm ----
        float z = 0.f;
        if (tid < 64) {
            float acc = __ldg(&proj_b[tid]);
            const float4* pw4 = (const float4*)proj_w + tid * 32;
            #pragma unroll
            for (int k = 0; k < 32; k++) {
                float4 f = feats4[k];
                float4 p = __ldg(&pw4[k]);
                acc += f.x * p.x + f.y * p.y + f.z * p.z + f.w * p.w;
            }
            z = gelu_exact(acc);
            lnred[tid] = z;
            lnred[64 + tid] = z * z;
        }
        __syncthreads();
        if (tid < 32) {
            float s = lnred[tid] + lnred[tid + 32];
            float q = lnred[64 + tid] + lnred[96 + tid];
            #pragma unroll
            for (int o = 16; o; o >>= 1) {
                s += __shfl_xor_sync(0xffffffffu, s, o);
                q += __shfl_xor_sync(0xffffffffu, q, o);
            }
            if (tid == 0) {
                float mu  = s * (1.0f / 64.0f);
                float var = q * (1.0f / 64.0f) - mu * mu;
                lnstats[0] = mu;
                lnstats[1] = rsqrtf(var + 1e-5f);
            }
        }
        __syncthreads();
        if (tid < 64)
            out[row * 64 + tid] = (z - lnstats[0]) * lnstats[1] * __ldg(&gamma[tid]) + __ldg(&beta[tid]);
        __syncthreads();
    }
}

// ---------------------------------------------------------------------------
extern "C" void kernel_launch(void* const* d_in, const int* in_sizes, int n_in,
                              void* d_out, int out_size)
{
    (void)in_sizes; (void)n_in; (void)out_size;
    const int*   x_idx  = (const int*)  d_in[0];
    const float* emb    = (const float*)d_in[1];
    const float* cw[4], *cb[4], *aw[4];
    for (int i = 0; i < 4; i++) {
        cw[i] = (const float*)d_in[2 + 4 * i];
        cb[i] = (const float*)d_in[3 + 4 * i];
        aw[i] = (const float*)d_in[4 + 4 * i];
        // att_b is a constant shift inside softmax -> cancels
    }
    const float* proj_w = (const float*)d_in[18];
    const float* proj_b = (const float*)d_in[19];
    const float* gamma  = (const float*)d_in[20];
    const float* beta   = (const float*)d_in[21];

    build_lut_kernel<<<488, 256>>>(emb,
        cw[0], cb[0], aw[0],
        cw[1], cb[1], aw[1],
        cw[2], cb[2], aw[2],
        cw[3], cb[3], aw[3]);

    combine_s4_kernel<<<13, 256>>>();

    seqcnn_main<<<GRID_MAIN, 256>>>(x_idx, proj_w, proj_b, gamma, beta, (float*)d_out);
}

// round 4
// speedup vs baseline: 1.4442x; 1.0196x over previous
#include <cuda_runtime.h>
#include <math.h>

#define BATCH 4096
#define SEQL 512
#define NTUP 3900            // 25 + 125 + 625 + 3125
#define WH 152               // hist stride (25 + 125, padded)
#define GRID_MAIN 740

__device__ __align__(128) float  g_lutH[NTUP * 32];   // gelu(conv+b) per (tuple, filter)
__device__ __align__(128) float  g_lutS[NTUP];        // exp(attention score) per tuple
__device__ __align__(128) float4 g_lutS4[3125];       // combined exp-scores keyed by 5-gram code
__device__ unsigned g_row_ctr;

__device__ __forceinline__ float gelu_exact(float x) {
    return 0.5f * x * (1.0f + erff(x * 0.70710678118654752440f));
}

// ---------------------------------------------------------------------------
// Kernel A: build per-branch LUTs via factored partial dot products.
// Block handles a chunk of one branch. pdot[j][t][lane] staged in smem.
// ---------------------------------------------------------------------------
template <int KS>
__device__ void build_branch(
    int blk, int nblk, int baseS, int baseH, int ntup,
    const float* __restrict__ emb, const float* __restrict__ W,
    const float* __restrict__ Bv, const float* __restrict__ A,
    float* pdot /* [KS*5*32] */, float* sbias, float* satt)
{
    const int tid = threadIdx.x, lane = tid & 31, warp = tid >> 5;

    // stage pdot: KS*5*32 entries, each an 8-long dot product
    for (int i = tid; i < KS * 5 * 32; i += 256) {
        int l8 = i & 31;
        int t  = (i >> 5) % 5;
        int j  = i / 160;
        float acc = 0.f;
        #pragma unroll
        for (int c = 0; c < 8; c++)
            acc += __ldg(&emb[t * 8 + c]) * __ldg(&W[l8 * 8 * KS + c * KS + j]);
        pdot[j * 160 + t * 32 + l8] = acc;
    }
    if (tid < 32) { sbias[tid] = Bv[tid]; satt[tid] = A[tid]; }
    __syncthreads();

    int chunk = (ntup + nblk - 1) / nblk;
    int lo = blk * chunk;
    int hi = min(lo + chunk, ntup);

    for (int code = lo + warp; code < hi; code += 8) {
        float acc = sbias[lane];
        int c = code;
        #pragma unroll
        for (int j = 0; j < KS; j++) {
            int t = c % 5; c /= 5;
            acc += pdot[j * 160 + t * 32 + lane];
        }
        float h = gelu_exact(acc);
        g_lutH[baseH + code * 32 + lane] = h;

        float sv = h * satt[lane];
        #pragma unroll
        for (int o = 16; o; o >>= 1) sv += __shfl_xor_sync(0xffffffffu, sv, o);
        if (lane == 0) g_lutS[baseS + code] = __expf(sv);   // exp folded into LUT
    }
}

__global__ __launch_bounds__(256) void build_lut_kernel(
    const float* __restrict__ emb,
    const float* __restrict__ w0, const float* __restrict__ b0, const float* __restrict__ a0,
    const float* __restrict__ w1, const float* __restrict__ b1, const float* __restrict__ a1,
    const float* __restrict__ w2, const float* __restrict__ b2, const float* __restrict__ a2,
    const float* __restrict__ w3, const float* __restrict__ b3, const float* __restrict__ a3)
{
    __shared__ float pdot[5 * 5 * 32];   // max KS=5
    __shared__ float sbias[32], satt[32];
    int b = blockIdx.x;
    if (b == 0)      build_branch<2>(0,      1,  0,   0,     25,   emb, w0, b0, a0, pdot, sbias, satt);
    else if (b == 1) build_branch<3>(0,      1,  25,  800,   125,  emb, w1, b1, a1, pdot, sbias, satt);
    else if (b < 8)  build_branch<4>(b - 2,  6,  150, 4800,  625,  emb, w2, b2, a2, pdot, sbias, satt);
    else             build_branch<5>(b - 8,  24, 775, 24800, 3125, emb, w3, b3, a3, pdot, sbias, satt);
}

// ---------------------------------------------------------------------------
// Kernel B: combine per-branch exp-scores keyed by 5-gram code; reset counter.
// ---------------------------------------------------------------------------
__global__ void combine_s4_kernel()
{
    int c = blockIdx.x * blockDim.x + threadIdx.x;
    if (c == 0) g_row_ctr = 0;
    if (c >= 3125) return;
    float4 s;
    s.x = g_lutS[        c % 25 ];
    s.y = g_lutS[ 25  +  c % 125];
    s.z = g_lutS[ 150 +  c % 625];
    s.w = g_lutS[ 775 +  c      ];
    g_lutS4[c] = s;
}

// ---------------------------------------------------------------------------
// Kernel C: persistent main kernel, dynamic row stealing. No exp in hot loop.
// ---------------------------------------------------------------------------
__global__ __launch_bounds__(256, 5) void seqcnn_main(
    const int*   __restrict__ x_idx,
    const float* __restrict__ proj_w,   // [64][128]
    const float* __restrict__ proj_b,
    const float* __restrict__ gamma,
    const float* __restrict__ beta,
    float*       __restrict__ out)
{
    __shared__ unsigned char xrow[SEQL + 8];
    __shared__ unsigned      code45[SEQL];   // c4 | c5<<16
    __shared__ float2        swv2[SEQL];     // exp weights (ks4, ks5)
    __shared__ float         hist[8 * WH];   // per-warp ks2/ks3 weight histograms
    __shared__ float4        zred[8];        // per-warp Z partials (4 branches)
    __shared__ float4        partial[4][64]; // [branch][warp*8 + fl]
    __shared__ float4        feats4[32];     // 128 pooled features
    __shared__ float         lnred[128];
    __shared__ float         lnstats[2];
    __shared__ unsigned      row_sh;

    const int tid = threadIdx.x, lane = tid & 31, warp = tid >> 5;
    const int grp = lane >> 3, fl = lane & 7;
    const float4* lutH4 = (const float4*)g_lutH;

    for (;;) {
        if (tid == 0) row_sh = atomicAdd(&g_row_ctr, 1u);
        __syncthreads();
        const unsigned row = row_sh;
        if (row >= BATCH) break;

        // ---- phase 0: stage row + zero hist ----
        for (int l = tid; l < SEQL; l += 256)
            xrow[l] = (unsigned char)x_idx[row * SEQL + l];
        if (tid < 8) xrow[SEQL + tid] = 0;
        for (int i = tid; i < 8 * WH; i += 256) hist[i] = 0.f;
        __syncthreads();

        // ---- phase 1: codes + exp-weight gather; hist ks2/3; stash ks4/5 ----
        float4 sum4 = {0.f, 0.f, 0.f, 0.f};
        float* histW = hist + warp * WH;
        for (int l = tid; l < 511; l += 256) {
            int x0 = xrow[l], x1 = xrow[l+1], x2 = xrow[l+2], x3 = xrow[l+3], x4 = xrow[l+4];
            int c2 = x0 + 5 * x1;
            int c3 = c2 + 25 * x2;
            int c4 = c3 + 125 * x3;
            int c5 = c4 + 625 * x4;
            float4 e = __ldg(&g_lutS4[c5]);   // already exponentiated
            if (l >= 508) e.w = 0.f;          // ks=5 valid l < 508
            if (l >= 509) e.z = 0.f;          // ks=4 valid l < 509
            if (l >= 510) e.y = 0.f;          // ks=3 valid l < 510
            atomicAdd(&histW[c2], e.x);
            atomicAdd(&histW[25 + c3], e.y);
            swv2[l] = make_float2(e.z, e.w);
            code45[l] = (unsigned)(c4 | (c5 << 16));
            sum4.x += e.x; sum4.y += e.y; sum4.z += e.z; sum4.w += e.w;
        }
        #pragma unroll
        for (int o = 16; o; o >>= 1) {
            sum4.x += __shfl_xor_sync(0xffffffffu, sum4.x, o);
            sum4.y += __shfl_xor_sync(0xffffffffu, sum4.y, o);
            sum4.z += __shfl_xor_sync(0xffffffffu, sum4.z, o);
            sum4.w += __shfl_xor_sync(0xffffffffu, sum4.w, o);
        }
        if (lane == 0) zred[warp] = sum4;
        __syncthreads();

        // ---- phase 2a: sparse pooling for ks4/ks5 ----
        float4 a2 = {0,0,0,0}, a3 = a2;
        for (int base = warp * 4 + grp; base < 509; base += 32) {
            unsigned cd = code45[base];
            float2 w = swv2[base];
            int c4 = cd & 0xffff, c5 = cd >> 16;
            float4 h2 = __ldg(&lutH4[1200 + (c4 << 3) + fl]);
            float4 h3 = __ldg(&lutH4[6200 + (c5 << 3) + fl]);
            a2.x += w.x * h2.x; a2.y += w.x * h2.y; a2.z += w.x * h2.z; a2.w += w.x * h2.w;
            a3.x += w.y * h3.x; a3.y += w.y * h3.y; a3.z += w.y * h3.z; a3.w += w.y * h3.w;
        }

        // ---- phase 2b: dense pooling for ks2/ks3 over 150 codes ----
        float4 a0 = {0,0,0,0}, a1 = a0;
        for (int code = warp * 4 + grp; code < 150; code += 32) {
            float wsum = 0.f;
            #pragma unroll
            for (int w8 = 0; w8 < 8; w8++) wsum += hist[w8 * WH + code];
            if (code < 25) {
                float4 h = __ldg(&lutH4[(code << 3) + fl]);
                a0.x += wsum * h.x; a0.y += wsum * h.y; a0.z += wsum * h.z; a0.w += wsum * h.w;
            } else {
                float4 h = __ldg(&lutH4[200 + ((code - 25) << 3) + fl]);
                a1.x += wsum * h.x; a1.y += wsum * h.y; a1.z += wsum * h.z; a1.w += wsum * h.w;
            }
        }

        // reduce across the 4 groups within each warp
        #pragma unroll
        for (int o = 8; o <= 16; o <<= 1) {
            a0.x += __shfl_xor_sync(0xffffffffu, a0.x, o); a0.y += __shfl_xor_sync(0xffffffffu, a0.y, o);
            a0.z += __shfl_xor_sync(0xffffffffu, a0.z, o); a0.w += __shfl_xor_sync(0xffffffffu, a0.w, o);
            a1.x += __shfl_xor_sync(0xffffffffu, a1.x, o); a1.y += __shfl_xor_sync(0xffffffffu, a1.y, o);
            a1.z += __shfl_xor_sync(0xffffffffu, a1.z, o); a1.w += __shfl_xor_sync(0xffffffffu, a1.w, o);
            a2.x += __shfl_xor_sync(0xffffffffu, a2.x, o); a2.y += __shfl_xor_sync(0xffffffffu, a2.y, o);
            a2.z += __shfl_xor_sync(0xffffffffu, a2.z, o); a2.w += __shfl_xor_sync(0xffffffffu, a2.w, o);
            a3.x += __shfl_xor_sync(0xffffffffu, a3.x, o); a3.y += __shfl_xor_sync(0xffffffffu, a3.y, o);
            a3.z += __shfl_xor_sync(0xffffffffu, a3.z, o); a3.w += __shfl_xor_sync(0xffffffffu, a3.w, o);
        }
        if (grp == 0) {
            partial[0][warp * 8 + fl] = a0;
            partial[1][warp * 8 + fl] = a1;
            partial[2][warp * 8 + fl] = a2;
            partial[3][warp * 8 + fl] = a3;
        }
        __syncthreads();

        // ---- combine warps + normalize by Z ----
        if (tid < 32) {
            int br = tid >> 3, f = tid & 7;
            float4 s = {0,0,0,0};
            #pragma unroll
            for (int w8 = 0; w8 < 8; w8++) {
                float4 p = partial[br][w8 * 8 + f];
                s.x += p.x; s.y += p.y; s.z += p.z; s.w += p.w;
            }
            float4 zt = zred[0];
            #pragma unroll
            for (int w8 = 1; w8 < 8; w8++) {
                float4 zz = zred[w8];
                zt.x += zz.x; zt.y += zz.y; zt.z += zz.z; zt.w += zz.w;
            }
            float Z = (br == 0) ? zt.x : (br == 1) ? zt.y : (br == 2) ? zt.z : zt.w;
            float iz = 1.0f / Z;
            s.x *= iz; s.y *= iz; s.z *= iz; s.w *= iz;
            feats4[br * 8 + f] = s;
        }
        __syncthreads();

        // ---- proj (128->64) + gelu + layernorm ----
        float z = 0.f;
        if (tid < 64) {
            float acc = __ldg(&proj_b[tid]);
            const float4* pw4 = (const float4*)proj_w + tid * 32;
            #pragma unroll
            for (int k = 0; k < 32; k++) {
                float4 f = feats4[k];
                float4 p = __ldg(&pw4[k]);
                acc += f.x * p.x + f.y * p.y + f.z * p.z + f.w * p.w;
            }
            z = gelu_exact(acc);
            lnred[tid] = z;
            lnred[64 + tid] = z * z;
        }
        __syncthreads();
        if (tid < 32) {
            float s = lnred[tid] + lnred[tid + 32];
            float q = lnred[64 + tid] + lnred[96 + tid];
            #pragma unroll
            for (int o = 16; o; o >>= 1) {
                s += __shfl_xor_sync(0xffffffffu, s, o);
                q += __shfl_xor_sync(0xffffffffu, q, o);
            }
            if (tid == 0) {
                float mu  = s * (1.0f / 64.0f);
                float var = q * (1.0f / 64.0f) - mu * mu;
                lnstats[0] = mu;
                lnstats[1] = rsqrtf(var + 1e-5f);
            }
        }
        __syncthreads();
        if (tid < 64)
            out[row * 64 + tid] = (z - lnstats[0]) * lnstats[1] * __ldg(&gamma[tid]) + __ldg(&beta[tid]);
        __syncthreads();
    }
}

// ---------------------------------------------------------------------------
extern "C" void kernel_launch(void* const* d_in, const int* in_sizes, int n_in,
                              void* d_out, int out_size)
{
    (void)in_sizes; (void)n_in; (void)out_size;
    const int*   x_idx  = (const int*)  d_in[0];
    const float* emb    = (const float*)d_in[1];
    const float* cw[4], *cb[4], *aw[4];
    for (int i = 0; i < 4; i++) {
        cw[i] = (const float*)d_in[2 + 4 * i];
        cb[i] = (const float*)d_in[3 + 4 * i];
        aw[i] = (const float*)d_in[4 + 4 * i];
        // att_b is a constant shift inside softmax -> cancels
    }
    const float* proj_w = (const float*)d_in[18];
    const float* proj_b = (const float*)d_in[19];
    const float* gamma  = (const float*)d_in[20];
    const float* beta   = (const float*)d_in[21];

    build_lut_kernel<<<32, 256>>>(emb,
        cw[0], cb[0], aw[0],
        cw[1], cb[1], aw[1],
        cw[2], cb[2], aw[2],
        cw[3], cb[3], aw[3]);

    combine_s4_kernel<<<13, 256>>>();

    seqcnn_main<<<GRID_MAIN, 256>>>(x_idx, proj_w, proj_b, gamma, beta, (float*)d_out);
}

// round 5
// speedup vs baseline: 2.1020x; 1.4555x over previous
#include <cuda_runtime.h>
#include <math.h>

#define BATCH 4096
#define SEQL 512
#define NTUP 3900            // 25 + 125 + 625 + 3125
#define WH 152               // hist stride (25 + 125, padded)
#define GRID_MAIN 740

__device__ __align__(128) float  g_H23[150 * 32];     // plain gelu(conv+b) for ks2, ks3
__device__ __align__(128) float  g_F4[626 * 32];      // S4*h4, record 625 = zeros
__device__ __align__(128) float  g_F5[3126 * 32];     // S5*h5, record 3125 = zeros
__device__ __align__(128) float  g_lutS[NTUP];        // exp(score) per tuple
__device__ __align__(128) float4 g_lutS4[3125];       // packed exp-scores by 5-gram code
__device__ __align__(128) float  g_Wt[128 * 64];      // proj_w transposed
__device__ unsigned g_row_ctr;

__device__ __forceinline__ float gelu_exact(float x) {
    return 0.5f * x * (1.0f + erff(x * 0.70710678118654752440f));
}
__device__ __forceinline__ unsigned long long f2add(unsigned long long a, unsigned long long b) {
    unsigned long long r; asm("add.rn.f32x2 %0,%1,%2;" : "=l"(r) : "l"(a), "l"(b)); return r;
}
__device__ __forceinline__ unsigned long long f2fma(unsigned long long a, unsigned long long b, unsigned long long c) {
    unsigned long long r; asm("fma.rn.f32x2 %0,%1,%2,%3;" : "=l"(r) : "l"(a), "l"(b), "l"(c)); return r;
}
__device__ __forceinline__ unsigned long long f2pack(float lo, float hi) {
    unsigned long long r; asm("mov.b64 %0,{%1,%2};" : "=l"(r) : "f"(lo), "f"(hi)); return r;
}
union U2F4 { ulonglong2 u; float4 f; };

// ---------------------------------------------------------------------------
// Kernel A: build per-branch LUTs via factored partial dot products.
// ---------------------------------------------------------------------------
template <int KS, bool SCALE>
__device__ void build_branch(
    int blk, int nblk, int baseS, float* __restrict__ HOut, int ntup,
    const float* __restrict__ emb, const float* __restrict__ W,
    const float* __restrict__ Bv, const float* __restrict__ A,
    float* pdot, float* sbias, float* satt)
{
    const int tid = threadIdx.x, lane = tid & 31, warp = tid >> 5;

    for (int i = tid; i < KS * 5 * 32; i += 256) {
        int l8 = i & 31;
        int t  = (i >> 5) % 5;
        int j  = i / 160;
        float acc = 0.f;
        #pragma unroll
        for (int c = 0; c < 8; c++)
            acc += __ldg(&emb[t * 8 + c]) * __ldg(&W[l8 * 8 * KS + c * KS + j]);
        pdot[j * 160 + t * 32 + l8] = acc;
    }
    if (tid < 32) { sbias[tid] = Bv[tid]; satt[tid] = A[tid]; }
    __syncthreads();

    int chunk = (ntup + nblk - 1) / nblk;
    int lo = blk * chunk;
    int hi = min(lo + chunk, ntup);

    for (int code = lo + warp; code < hi; code += 8) {
        float acc = sbias[lane];
        int c = code;
        #pragma unroll
        for (int j = 0; j < KS; j++) {
            int t = c % 5; c /= 5;
            acc += pdot[j * 160 + t * 32 + lane];
        }
        float h = gelu_exact(acc);

        float sv = h * satt[lane];
        #pragma unroll
        for (int o = 16; o; o >>= 1) sv += __shfl_xor_sync(0xffffffffu, sv, o);
        float e = __expf(sv);                 // all lanes hold full sum

        HOut[code * 32 + lane] = SCALE ? h * e : h;
        if (lane == 0) g_lutS[baseS + code] = e;
    }
}

__global__ __launch_bounds__(256) void build_lut_kernel(
    const float* __restrict__ emb,
    const float* __restrict__ w0, const float* __restrict__ b0, const float* __restrict__ a0,
    const float* __restrict__ w1, const float* __restrict__ b1, const float* __restrict__ a1,
    const float* __restrict__ w2, const float* __restrict__ b2, const float* __restrict__ a2,
    const float* __restrict__ w3, const float* __restrict__ b3, const float* __restrict__ a3)
{
    __shared__ float pdot[5 * 5 * 32];
    __shared__ float sbias[32], satt[32];
    int b = blockIdx.x;
    if (b == 0)      build_branch<2, false>(0,     1,  0,   g_H23,            25,   emb, w0, b0, a0, pdot, sbias, satt);
    else if (b == 1) build_branch<3, false>(0,     1,  25,  g_H23 + 25 * 32,  125,  emb, w1, b1, a1, pdot, sbias, satt);
    else if (b < 8)  build_branch<4, true >(b - 2, 6,  150, g_F4,             625,  emb, w2, b2, a2, pdot, sbias, satt);
    else             build_branch<5, true >(b - 8, 24, 775, g_F5,             3125, emb, w3, b3, a3, pdot, sbias, satt);
}

// ---------------------------------------------------------------------------
// Kernel B: pack score LUT, transpose proj_w, zero dummy records, reset ctr.
// ---------------------------------------------------------------------------
__global__ void combine_s4_kernel(const float* __restrict__ proj_w)
{
    int i = blockIdx.x * blockDim.x + threadIdx.x;
    if (i == 0) g_row_ctr = 0;
    if (i < 3125) {
        float4 s;
        s.x = g_lutS[        i % 25 ];
        s.y = g_lutS[ 25  +  i % 125];
        s.z = g_lutS[ 150 +  i % 625];
        s.w = g_lutS[ 775 +  i      ];
        g_lutS4[i] = s;
    } else if (i < 3125 + 8192) {
        int j = i - 3125;
        int k = j >> 6, o = j & 63;
        g_Wt[j] = proj_w[o * 128 + k];
    } else if (i < 3125 + 8192 + 32) {
        g_F4[625 * 32 + (i - 3125 - 8192)] = 0.f;
    } else if (i < 3125 + 8192 + 64) {
        g_F5[3125 * 32 + (i - 3125 - 8192 - 32)] = 0.f;
    }
}

// ---------------------------------------------------------------------------
// Kernel C: persistent main kernel.
// ---------------------------------------------------------------------------
__global__ __launch_bounds__(256, 6) void seqcnn_main(
    const int*   __restrict__ x_idx,
    const float* __restrict__ proj_b,
    const float* __restrict__ gamma,
    const float* __restrict__ beta,
    float*       __restrict__ out)
{
    __shared__ unsigned char xrow[SEQL + 8];
    __shared__ unsigned      code45[SEQL];       // c4 | c5<<10 (with dummy redirects)
    __shared__ float         hist[8 * WH];
    __shared__ float4        zred[8];
    __shared__ float4        partial[4][64];
    __shared__ float4        feats4[32];         // viewed as float[128]
    __shared__ float         prsum[256];
    __shared__ float         lnred[128];
    __shared__ float         lnstats[2];
    __shared__ unsigned      row_sh;

    const int tid = threadIdx.x, lane = tid & 31, warp = tid >> 5;
    const int grp = lane >> 3, fl = lane & 7;
    const ulonglong2* F4v  = (const ulonglong2*)g_F4;
    const ulonglong2* F5v  = (const ulonglong2*)g_F5;
    const ulonglong2* H23v = (const ulonglong2*)g_H23;

    for (;;) {
        if (tid == 0) row_sh = atomicAdd(&g_row_ctr, 1u);
        __syncthreads();
        const unsigned row = row_sh;
        if (row >= BATCH) break;

        // ---- phase 0 ----
        for (int l = tid; l < SEQL; l += 256)
            xrow[l] = (unsigned char)x_idx[row * SEQL + l];
        if (tid < 8) xrow[SEQL + tid] = 0;
        for (int i = tid; i < 8 * WH; i += 256) hist[i] = 0.f;
        __syncthreads();

        // ---- phase 1: codes + exp-weight gather + hist + Z; uniform 512 ----
        float4 sum4 = {0.f, 0.f, 0.f, 0.f};
        float* histW = hist + warp * WH;
        #pragma unroll
        for (int it = 0; it < 2; it++) {
            int l = tid + it * 256;
            int x0 = xrow[l], x1 = xrow[l+1], x2 = xrow[l+2], x3 = xrow[l+3], x4 = xrow[l+4];
            int c2 = x0 + 5 * x1;
            int c3 = c2 + 25 * x2;
            int c4 = c3 + 125 * x3;
            int c5 = c4 + 625 * x4;
            float4 e = __ldg(&g_lutS4[c5]);
            if (l >= 508) e.w = 0.f;
            if (l >= 509) e.z = 0.f;
            if (l >= 510) e.y = 0.f;
            if (l >= 511) e.x = 0.f;
            atomicAdd(&histW[c2], e.x);
            atomicAdd(&histW[25 + c3], e.y);
            int c4s = (l >= 509) ? 625  : c4;
            int c5s = (l >= 508) ? 3125 : c5;
            code45[l] = (unsigned)(c4s | (c5s << 10));
            sum4.x += e.x; sum4.y += e.y; sum4.z += e.z; sum4.w += e.w;
        }
        #pragma unroll
        for (int o = 16; o; o >>= 1) {
            sum4.x += __shfl_xor_sync(0xffffffffu, sum4.x, o);
            sum4.y += __shfl_xor_sync(0xffffffffu, sum4.y, o);
            sum4.z += __shfl_xor_sync(0xffffffffu, sum4.z, o);
            sum4.w += __shfl_xor_sync(0xffffffffu, sum4.w, o);
        }
        if (lane == 0) zred[warp] = sum4;
        __syncthreads();

        // ---- phase 2a: ks4/ks5 pooling, pre-scaled tables, pure adds ----
        unsigned long long a4lo = 0, a4hi = 0, a5lo = 0, a5hi = 0;
        {
            // zero in f32x2 = 0ull (0.0f,0.0f bits) OK
            #pragma unroll 2
            for (int base = warp * 4 + grp; base < 512; base += 32) {
                unsigned cd = code45[base];
                int c4 = cd & 1023, c5 = cd >> 10;
                ulonglong2 f4 = __ldg(&F4v[c4 * 8 + fl]);
                ulonglong2 f5 = __ldg(&F5v[c5 * 8 + fl]);
                a4lo = f2add(a4lo, f4.x); a4hi = f2add(a4hi, f4.y);
                a5lo = f2add(a5lo, f5.x); a5hi = f2add(a5hi, f5.y);
            }
        }

        // ---- phase 2b: ks2/ks3 dense over 150 codes ----
        unsigned long long a2lo = 0, a2hi = 0, a3lo = 0, a3hi = 0;
        for (int code = warp * 4 + grp; code < 150; code += 32) {
            float wsum = 0.f;
            #pragma unroll
            for (int w8 = 0; w8 < 8; w8++) wsum += hist[w8 * WH + code];
            unsigned long long w2 = f2pack(wsum, wsum);
            ulonglong2 h = __ldg(&H23v[code * 8 + fl]);
            if (code < 25) { a2lo = f2fma(w2, h.x, a2lo); a2hi = f2fma(w2, h.y, a2hi); }
            else           { a3lo = f2fma(w2, h.x, a3lo); a3hi = f2fma(w2, h.y, a3hi); }
        }

        // reduce across the 4 groups within each warp (f32x2 adds)
        #pragma unroll
        for (int o = 8; o <= 16; o <<= 1) {
            a2lo = f2add(a2lo, __shfl_xor_sync(0xffffffffu, a2lo, o));
            a2hi = f2add(a2hi, __shfl_xor_sync(0xffffffffu, a2hi, o));
            a3lo = f2add(a3lo, __shfl_xor_sync(0xffffffffu, a3lo, o));
            a3hi = f2add(a3hi, __shfl_xor_sync(0xffffffffu, a3hi, o));
            a4lo = f2add(a4lo, __shfl_xor_sync(0xffffffffu, a4lo, o));
            a4hi = f2add(a4hi, __shfl_xor_sync(0xffffffffu, a4hi, o));
            a5lo = f2add(a5lo, __shfl_xor_sync(0xffffffffu, a5lo, o));
            a5hi = f2add(a5hi, __shfl_xor_sync(0xffffffffu, a5hi, o));
        }
        if (grp == 0) {
            U2F4 u;
            u.u.x = a2lo; u.u.y = a2hi; partial[0][warp * 8 + fl] = u.f;
            u.u.x = a3lo; u.u.y = a3hi; partial[1][warp * 8 + fl] = u.f;
            u.u.x = a4lo; u.u.y = a4hi; partial[2][warp * 8 + fl] = u.f;
            u.u.x = a5lo; u.u.y = a5hi; partial[3][warp * 8 + fl] = u.f;
        }
        __syncthreads();

        // ---- combine warps + normalize by Z ----
        if (tid < 32) {
            int br = tid >> 3, f = tid & 7;
            float4 s = {0,0,0,0};
            #pragma unroll
            for (int w8 = 0; w8 < 8; w8++) {
                float4 p = partial[br][w8 * 8 + f];
                s.x += p.x; s.y += p.y; s.z += p.z; s.w += p.w;
            }
            float4 zt = zred[0];
            #pragma unroll
            for (int w8 = 1; w8 < 8; w8++) {
                float4 zz = zred[w8];
                zt.x += zz.x; zt.y += zz.y; zt.z += zz.z; zt.w += zz.w;
            }
            float Z = (br == 0) ? zt.x : (br == 1) ? zt.y : (br == 2) ? zt.z : zt.w;
            float iz = 1.0f / Z;
            s.x *= iz; s.y *= iz; s.z *= iz; s.w *= iz;
            feats4[br * 8 + f] = s;
        }
        __syncthreads();

        // ---- proj (128->64) across all 256 threads, transposed weights ----
        {
            const float* sfeat = (const float*)feats4;
            int o = tid & 63, q = tid >> 6;
            const float* wt = g_Wt + (q * 32) * 64 + o;
            const float* fk = sfeat + q * 32;
            float acc = 0.f;
            #pragma unroll
            for (int kk = 0; kk < 32; kk++)
                acc = fmaf(fk[kk], __ldg(&wt[kk * 64]), acc);
            prsum[tid] = acc;
        }
        __syncthreads();

        // ---- gelu + layernorm ----
        float z = 0.f;
        if (tid < 64) {
            z = __ldg(&proj_b[tid]) + prsum[tid] + prsum[64 + tid] + prsum[128 + tid] + prsum[192 + tid];
            z = gelu_exact(z);
            lnred[tid] = z;
            lnred[64 + tid] = z * z;
        }
        __syncthreads();
        if (tid < 32) {
            float s = lnred[tid] + lnred[tid + 32];
            float q = lnred[64 + tid] + lnred[96 + tid];
            #pragma unroll
            for (int o = 16; o; o >>= 1) {
                s += __shfl_xor_sync(0xffffffffu, s, o);
                q += __shfl_xor_sync(0xffffffffu, q, o);
            }
            if (tid == 0) {
                float mu  = s * (1.0f / 64.0f);
                float var = q * (1.0f / 64.0f) - mu * mu;
                lnstats[0] = mu;
                lnstats[1] = rsqrtf(var + 1e-5f);
            }
        }
        __syncthreads();
        if (tid < 64)
            out[row * 64 + tid] = (z - lnstats[0]) * lnstats[1] * __ldg(&gamma[tid]) + __ldg(&beta[tid]);
        __syncthreads();
    }
}

// ---------------------------------------------------------------------------
extern "C" void kernel_launch(void* const* d_in, const int* in_sizes, int n_in,
                              void* d_out, int out_size)
{
    (void)in_sizes; (void)n_in; (void)out_size;
    const int*   x_idx  = (const int*)  d_in[0];
    const float* emb    = (const float*)d_in[1];
    const float* cw[4], *cb[4], *aw[4];
    for (int i = 0; i < 4; i++) {
        cw[i] = (const float*)d_in[2 + 4 * i];
        cb[i] = (const float*)d_in[3 + 4 * i];
        aw[i] = (const float*)d_in[4 + 4 * i];
    }
    const float* proj_w = (const float*)d_in[18];
    const float* proj_b = (const float*)d_in[19];
    const float* gamma  = (const float*)d_in[20];
    const float* beta   = (const float*)d_in[21];

    build_lut_kernel<<<32, 256>>>(emb,
        cw[0], cb[0], aw[0],
        cw[1], cb[1], aw[1],
        cw[2], cb[2], aw[2],
        cw[3], cb[3], aw[3]);

    combine_s4_kernel<<<45, 256>>>(proj_w);

    seqcnn_main<<<GRID_MAIN, 256>>>(x_idx, proj_b, gamma, beta, (float*)d_out);
}

// round 6
// speedup vs baseline: 2.1279x; 1.0123x over previous
#include <cuda_runtime.h>
#include <math.h>

#define BATCH 4096
#define SEQL 512
#define WH 152               // hist stride (25 + 125, padded)
#define GRID_MAIN 888

__device__ __align__(128) float  g_H23[150 * 32];     // plain gelu(conv+b) for ks2, ks3
__device__ __align__(128) float  g_F4[626 * 32];      // S4*h4, record 625 = zeros
__device__ __align__(128) float  g_F5[3126 * 32];     // S5*h5, record 3125 = zeros
__device__ __align__(128) float4 g_lutS4[3125];       // packed exp-scores by 5-gram code
__device__ __align__(128) float  g_Wt[128 * 64];      // proj_w transposed
__device__ unsigned g_row_ctr;

__device__ __forceinline__ float gelu_exact(float x) {
    return 0.5f * x * (1.0f + erff(x * 0.70710678118654752440f));
}
__device__ __forceinline__ unsigned long long f2add(unsigned long long a, unsigned long long b) {
    unsigned long long r; asm("add.rn.f32x2 %0,%1,%2;" : "=l"(r) : "l"(a), "l"(b)); return r;
}
__device__ __forceinline__ unsigned long long f2fma(unsigned long long a, unsigned long long b, unsigned long long c) {
    unsigned long long r; asm("fma.rn.f32x2 %0,%1,%2,%3;" : "=l"(r) : "l"(a), "l"(b), "l"(c)); return r;
}
__device__ __forceinline__ unsigned long long f2pack(float lo, float hi) {
    unsigned long long r; asm("mov.b64 %0,{%1,%2};" : "=l"(r) : "f"(lo), "f"(hi)); return r;
}
union U2F4 { ulonglong2 u; float4 f; };

// ---------------------------------------------------------------------------
// Fused setup kernel.
// Blocks 0..97 : 32 five-gram codes each (8 warps x 4 codes). Each warp
//                computes h2..h5 + e2..e5 for its code and writes all LUTs.
// Blocks 98..101: transpose proj_w into g_Wt.
// Block 102     : zero dummy records, reset row counter.
// ---------------------------------------------------------------------------
__global__ __launch_bounds__(256) void setup_kernel(
    const float* __restrict__ emb,
    const float* __restrict__ w0, const float* __restrict__ b0, const float* __restrict__ a0,
    const float* __restrict__ w1, const float* __restrict__ b1, const float* __restrict__ a1,
    const float* __restrict__ w2, const float* __restrict__ b2, const float* __restrict__ a2,
    const float* __restrict__ w3, const float* __restrict__ b3, const float* __restrict__ a3,
    const float* __restrict__ proj_w)
{
    const int b = blockIdx.x, tid = threadIdx.x, lane = tid & 31, warp = tid >> 5;

    if (b >= 98) {
        if (b < 102) {
            // Wt transpose: 8192 elements, 2048 per block
            int j0 = (b - 98) * 2048 + tid;
            #pragma unroll
            for (int r = 0; r < 8; r++) {
                int j = j0 + r * 256;
                int k = j >> 6, o = j & 63;
                g_Wt[j] = __ldg(&proj_w[o * 128 + k]);
            }
        } else {
            if (tid == 0) g_row_ctr = 0;
            if (tid < 32)      g_F4[625 * 32 + tid] = 0.f;
            else if (tid < 64) g_F5[3125 * 32 + (tid - 32)] = 0.f;
        }
        return;
    }

    // ---- stage partial dots for all 4 branches: 14 (branch,j) slots x 5 tokens x 32 filters
    __shared__ float pdall[14 * 160];
    __shared__ float sb[4][32], sa[4][32];
    for (int i = tid; i < 14 * 160; i += 256) {
        int l8 = i & 31;
        int t  = (i >> 5) % 5;
        int slot = i / 160;
        const float* W; int KS, j;
        if (slot < 2)      { W = w0; KS = 2; j = slot; }
        else if (slot < 5) { W = w1; KS = 3; j = slot - 2; }
        else if (slot < 9) { W = w2; KS = 4; j = slot - 5; }
        else               { W = w3; KS = 5; j = slot - 9; }
        float acc = 0.f;
        #pragma unroll
        for (int c = 0; c < 8; c++)
            acc += __ldg(&emb[t * 8 + c]) * __ldg(&W[l8 * 8 * KS + c * KS + j]);
        pdall[slot * 160 + t * 32 + l8] = acc;
    }
    if (tid < 128) {
        int br = tid >> 5, f = tid & 31;
        const float* Bv = (br == 0) ? b0 : (br == 1) ? b1 : (br == 2) ? b2 : b3;
        const float* Av = (br == 0) ? a0 : (br == 1) ? a1 : (br == 2) ? a2 : a3;
        sb[br][f] = __ldg(&Bv[f]);
        sa[br][f] = __ldg(&Av[f]);
    }
    __syncthreads();

    #pragma unroll
    for (int k = 0; k < 4; k++) {
        int c = b * 32 + warp * 4 + k;
        if (c >= 3125) break;
        int t0 = c % 5, r = c / 5;
        int t1 = r % 5; r /= 5;
        int t2 = r % 5; r /= 5;
        int t3 = r % 5, t4 = r / 5;

        float acc2 = sb[0][lane] + pdall[0*160 + t0*32 + lane] + pdall[1*160 + t1*32 + lane];
        float acc3 = sb[1][lane] + pdall[2*160 + t0*32 + lane] + pdall[3*160 + t1*32 + lane]
                                 + pdall[4*160 + t2*32 + lane];
        float acc4 = sb[2][lane] + pdall[5*160 + t0*32 + lane] + pdall[6*160 + t1*32 + lane]
                                 + pdall[7*160 + t2*32 + lane] + pdall[8*160 + t3*32 + lane];
        float acc5 = sb[3][lane] + pdall[9*160 + t0*32 + lane] + pdall[10*160 + t1*32 + lane]
                                 + pdall[11*160 + t2*32 + lane] + pdall[12*160 + t3*32 + lane]
                                 + pdall[13*160 + t4*32 + lane];
        float h2 = gelu_exact(acc2), h3 = gelu_exact(acc3);
        float h4 = gelu_exact(acc4), h5 = gelu_exact(acc5);

        float s2 = h2 * sa[0][lane], s3 = h3 * sa[1][lane];
        float s4 = h4 * sa[2][lane], s5 = h5 * sa[3][lane];
        #pragma unroll
        for (int o = 16; o; o >>= 1) {
            s2 += __shfl_xor_sync(0xffffffffu, s2, o);
            s3 += __shfl_xor_sync(0xffffffffu, s3, o);
            s4 += __shfl_xor_sync(0xffffffffu, s4, o);
            s5 += __shfl_xor_sync(0xffffffffu, s5, o);
        }
        float e2 = __expf(s2), e3 = __expf(s3), e4 = __expf(s4), e5 = __expf(s5);

        g_F5[c * 32 + lane] = h5 * e5;
        if (lane == 0) g_lutS4[c] = make_float4(e2, e3, e4, e5);
        if (c < 625) g_F4[c * 32 + lane] = h4 * e4;
        if (c < 125) g_H23[(25 + c) * 32 + lane] = h3;
        if (c < 25)  g_H23[c * 32 + lane] = h2;
    }
}

// ---------------------------------------------------------------------------
// Persistent main kernel.
// ---------------------------------------------------------------------------
__global__ __launch_bounds__(256, 6) void seqcnn_main(
    const int*   __restrict__ x_idx,
    const float* __restrict__ proj_b,
    const float* __restrict__ gamma,
    const float* __restrict__ beta,
    float*       __restrict__ out)
{
    __shared__ unsigned char xrow[SEQL + 8];
    __shared__ unsigned      code45[SEQL];       // c4 | c5<<10 (dummy redirects at edges)
    __shared__ float         hist[8 * WH];
    __shared__ float4        zred[8];
    __shared__ float4        partial[4][64];
    __shared__ float4        feats4[32];         // viewed as float[128]
    __shared__ float         prsum[256];
    __shared__ float         lnred[128];
    __shared__ float         lnstats[2];
    __shared__ unsigned      row_sh;

    const int tid = threadIdx.x, lane = tid & 31, warp = tid >> 5;
    const int grp = lane >> 3, fl = lane & 7;
    const ulonglong2* F4v  = (const ulonglong2*)g_F4;
    const ulonglong2* F5v  = (const ulonglong2*)g_F5;
    const ulonglong2* H23v = (const ulonglong2*)g_H23;

    for (;;) {
        if (tid == 0) row_sh = atomicAdd(&g_row_ctr, 1u);
        __syncthreads();
        const unsigned row = row_sh;
        if (row >= BATCH) break;

        // ---- phase 0 ----
        for (int l = tid; l < SEQL; l += 256)
            xrow[l] = (unsigned char)x_idx[row * SEQL + l];
        if (tid < 8) xrow[SEQL + tid] = 0;
        for (int i = tid; i < 8 * WH; i += 256) hist[i] = 0.f;
        __syncthreads();

        // ---- phase 1: both iterations' gathers issued up front ----
        float* histW = hist + warp * WH;
        const int la = tid, lb = tid + 256;
        int x0a = xrow[la], x1a = xrow[la+1], x2a = xrow[la+2], x3a = xrow[la+3], x4a = xrow[la+4];
        int x0b = xrow[lb], x1b = xrow[lb+1], x2b = xrow[lb+2], x3b = xrow[lb+3], x4b = xrow[lb+4];
        int c2a = x0a + 5*x1a, c3a = c2a + 25*x2a, c4a = c3a + 125*x3a, c5a = c4a + 625*x4a;
        int c2b = x0b + 5*x1b, c3b = c2b + 25*x2b, c4b = c3b + 125*x3b, c5b = c4b + 625*x4b;
        float4 ea = __ldg(&g_lutS4[c5a]);        // la < 256: no edge masks needed
        float4 eb = __ldg(&g_lutS4[c5b]);
        if (lb >= 508) eb.w = 0.f;
        if (lb >= 509) eb.z = 0.f;
        if (lb >= 510) eb.y = 0.f;
        if (lb >= 511) eb.x = 0.f;
        code45[la] = (unsigned)(c4a | (c5a << 10));
        int c4s = (lb >= 509) ? 625  : c4b;
        int c5s = (lb >= 508) ? 3125 : c5b;
        code45[lb] = (unsigned)(c4s | (c5s << 10));
        atomicAdd(&histW[c2a], ea.x);
        atomicAdd(&histW[25 + c3a], ea.y);
        atomicAdd(&histW[c2b], eb.x);
        atomicAdd(&histW[25 + c3b], eb.y);
        float4 sum4 = make_float4(ea.x + eb.x, ea.y + eb.y, ea.z + eb.z, ea.w + eb.w);
        #pragma unroll
        for (int o = 16; o; o >>= 1) {
            sum4.x += __shfl_xor_sync(0xffffffffu, sum4.x, o);
            sum4.y += __shfl_xor_sync(0xffffffffu, sum4.y, o);
            sum4.z += __shfl_xor_sync(0xffffffffu, sum4.z, o);
            sum4.w += __shfl_xor_sync(0xffffffffu, sum4.w, o);
        }
        if (lane == 0) zred[warp] = sum4;
        __syncthreads();

        // ---- phase 2a: ks4/ks5 pooling, 2-way interleaved for MLP ----
        unsigned long long a4lo = 0, a4hi = 0, a5lo = 0, a5hi = 0;
        unsigned long long b4lo = 0, b4hi = 0, b5lo = 0, b5hi = 0;
        {
            const int p = warp * 4 + grp;   // 0..31
            #pragma unroll 4
            for (int it = 0; it < 8; it++) {
                unsigned cd0 = code45[p + it * 64];
                unsigned cd1 = code45[p + it * 64 + 32];
                ulonglong2 f4a = __ldg(&F4v[(cd0 & 1023) * 8 + fl]);
                ulonglong2 f5a = __ldg(&F5v[(cd0 >> 10)  * 8 + fl]);
                ulonglong2 f4b = __ldg(&F4v[(cd1 & 1023) * 8 + fl]);
                ulonglong2 f5b = __ldg(&F5v[(cd1 >> 10)  * 8 + fl]);
                a4lo = f2add(a4lo, f4a.x); a4hi = f2add(a4hi, f4a.y);
                a5lo = f2add(a5lo, f5a.x); a5hi = f2add(a5hi, f5a.y);
                b4lo = f2add(b4lo, f4b.x); b4hi = f2add(b4hi, f4b.y);
                b5lo = f2add(b5lo, f5b.x); b5hi = f2add(b5hi, f5b.y);
            }
            a4lo = f2add(a4lo, b4lo); a4hi = f2add(a4hi, b4hi);
            a5lo = f2add(a5lo, b5lo); a5hi = f2add(a5hi, b5hi);
        }

        // ---- phase 2b: ks2/ks3 dense over 150 codes ----
        unsigned long long a2lo = 0, a2hi = 0, a3lo = 0, a3hi = 0;
        for (int code = warp * 4 + grp; code < 150; code += 32) {
            float wsum = 0.f;
            #pragma unroll
            for (int w8 = 0; w8 < 8; w8++) wsum += hist[w8 * WH + code];
            unsigned long long w2 = f2pack(wsum, wsum);
            ulonglong2 h = __ldg(&H23v[code * 8 + fl]);
            if (code < 25) { a2lo = f2fma(w2, h.x, a2lo); a2hi = f2fma(w2, h.y, a2hi); }
            else           { a3lo = f2fma(w2, h.x, a3lo); a3hi = f2fma(w2, h.y, a3hi); }
        }

        // reduce across the 4 groups within each warp
        #pragma unroll
        for (int o = 8; o <= 16; o <<= 1) {
            a2lo = f2add(a2lo, __shfl_xor_sync(0xffffffffu, a2lo, o));
            a2hi = f2add(a2hi, __shfl_xor_sync(0xffffffffu, a2hi, o));
            a3lo = f2add(a3lo, __shfl_xor_sync(0xffffffffu, a3lo, o));
            a3hi = f2add(a3hi, __shfl_xor_sync(0xffffffffu, a3hi, o));
            a4lo = f2add(a4lo, __shfl_xor_sync(0xffffffffu, a4lo, o));
            a4hi = f2add(a4hi, __shfl_xor_sync(0xffffffffu, a4hi, o));
            a5lo = f2add(a5lo, __shfl_xor_sync(0xffffffffu, a5lo, o));
            a5hi = f2add(a5hi, __shfl_xor_sync(0xffffffffu, a5hi, o));
        }
        if (grp == 0) {
            U2F4 u;
            u.u.x = a2lo; u.u.y = a2hi; partial[0][warp * 8 + fl] = u.f;
            u.u.x = a3lo; u.u.y = a3hi; partial[1][warp * 8 + fl] = u.f;
            u.u.x = a4lo; u.u.y = a4hi; partial[2][warp * 8 + fl] = u.f;
            u.u.x = a5lo; u.u.y = a5hi; partial[3][warp * 8 + fl] = u.f;
        }
        __syncthreads();

        // ---- combine warps + normalize by Z ----
        if (tid < 32) {
            int br = tid >> 3, f = tid & 7;
            float4 s = {0,0,0,0};
            #pragma unroll
            for (int w8 = 0; w8 < 8; w8++) {
                float4 p = partial[br][w8 * 8 + f];
                s.x += p.x; s.y += p.y; s.z += p.z; s.w += p.w;
            }
            float4 zt = zred[0];
            #pragma unroll
            for (int w8 = 1; w8 < 8; w8++) {
                float4 zz = zred[w8];
                zt.x += zz.x; zt.y += zz.y; zt.z += zz.z; zt.w += zz.w;
            }
            float Z = (br == 0) ? zt.x : (br == 1) ? zt.y : (br == 2) ? zt.z : zt.w;
            float iz = 1.0f / Z;
            s.x *= iz; s.y *= iz; s.z *= iz; s.w *= iz;
            feats4[br * 8 + f] = s;
        }
        __syncthreads();

        // ---- proj (128->64) across all 256 threads, transposed weights ----
        {
            const float* sfeat = (const float*)feats4;
            int o = tid & 63, q = tid >> 6;
            const float* wt = g_Wt + (q * 32) * 64 + o;
            const float* fk = sfeat + q * 32;
            float acc = 0.f;
            #pragma unroll
            for (int kk = 0; kk < 32; kk++)
                acc = fmaf(fk[kk], __ldg(&wt[kk * 64]), acc);
            prsum[tid] = acc;
        }
        __syncthreads();

        // ---- gelu + layernorm ----
        float z = 0.f;
        if (tid < 64) {
            z = __ldg(&proj_b[tid]) + prsum[tid] + prsum[64 + tid] + prsum[128 + tid] + prsum[192 + tid];
            z = gelu_exact(z);
            lnred[tid] = z;
            lnred[64 + tid] = z * z;
        }
        __syncthreads();
        if (tid < 32) {
            float s = lnred[tid] + lnred[tid + 32];
            float q = lnred[64 + tid] + lnred[96 + tid];
            #pragma unroll
            for (int o = 16; o; o >>= 1) {
                s += __shfl_xor_sync(0xffffffffu, s, o);
                q += __shfl_xor_sync(0xffffffffu, q, o);
            }
            if (tid == 0) {
                float mu  = s * (1.0f / 64.0f);
                float var = q * (1.0f / 64.0f) - mu * mu;
                lnstats[0] = mu;
                lnstats[1] = rsqrtf(var + 1e-5f);
            }
        }
        __syncthreads();
        if (tid < 64)
            out[row * 64 + tid] = (z - lnstats[0]) * lnstats[1] * __ldg(&gamma[tid]) + __ldg(&beta[tid]);
        __syncthreads();
    }
}

// ---------------------------------------------------------------------------
extern "C" void kernel_launch(void* const* d_in, const int* in_sizes, int n_in,
                              void* d_out, int out_size)
{
    (void)in_sizes; (void)n_in; (void)out_size;
    const int*   x_idx  = (const int*)  d_in[0];
    const float* emb    = (const float*)d_in[1];
    const float* cw[4], *cb[4], *aw[4];
    for (int i = 0; i < 4; i++) {
        cw[i] = (const float*)d_in[2 + 4 * i];
        cb[i] = (const float*)d_in[3 + 4 * i];
        aw[i] = (const float*)d_in[4 + 4 * i];
    }
    const float* proj_w = (const float*)d_in[18];
    const float* proj_b = (const float*)d_in[19];
    const float* gamma  = (const float*)d_in[20];
    const float* beta   = (const float*)d_in[21];

    setup_kernel<<<103, 256>>>(emb,
        cw[0], cb[0], aw[0],
        cw[1], cb[1], aw[1],
        cw[2], cb[2], aw[2],
        cw[3], cb[3], aw[3],
        proj_w);

    seqcnn_main<<<GRID_MAIN, 256>>>(x_idx, proj_b, gamma, beta, (float*)d_out);
}